// round 6
// baseline (speedup 1.0000x reference)
#include <cuda_runtime.h>
#include <math.h>

// SpectralEMA.  state_t = a*|state_{t-1}|*unit(x_t) + (1-rho)*x_t
//             = x_t * z_t / w_t,  z_t = a*m_{t-1} + omr*w_t,  m_t = |z_t|
// Real a (theta=0): m_t = rho*m_{t-1} + omr*w_t  -> affine scan; segments
// compose: m_out = rho^L * m_in + C_seg.
// Fused single kernel: G parallel segments per chain compute C (float2 =
// 2 features/thread, the proven-optimal load shape). The LAST block to
// finish in each (b, f-tile) column (detected with threadfence + atomic
// counter) combines all G segment coefficients -- g_C is still L2-hot --
// and writes the final output. No second launch.

#define G   16
#define UNR 4
#define MAX_BF   (32 * 4096)
#define MAX_COLS (MAX_BF / 512)

__device__ float        g_C[G * MAX_BF];
__device__ float2       g_lx[MAX_BF];      // x at s = S-1 per chain
__device__ unsigned int g_cnt[MAX_COLS];   // zero-init; finisher resets to 0

__device__ __forceinline__ float sigmoidf_(float x) {
    return 1.0f / (1.0f + expf(-x));
}

// |v| via single MUFU.RSQ
__device__ __forceinline__ float mag_(float vr, float vi) {
    float v2 = fmaxf(fmaf(vr, vr, vi * vi), 1e-37f);
    return v2 * rsqrtf(v2);
}

// ---------------- Fused kernel ----------------
__global__ __launch_bounds__(256)
void fused_kernel(const float* __restrict__ fr, const float* __restrict__ fi,
                  const float* __restrict__ ir, const float* __restrict__ ii,
                  const float* __restrict__ rho_logit,
                  const float* __restrict__ theta_raw,
                  float2* __restrict__ out, int S, int F, int L)
{
    int F2 = F >> 1;
    int f2 = blockIdx.x * blockDim.x + threadIdx.x;
    int b  = blockIdx.y;
    int g  = blockIdx.z;

    float2 rl  = __ldg((const float2*)rho_logit + f2);
    float rho0 = sigmoidf_(rl.x), rho1 = sigmoidf_(rl.y);
    float om0  = 1.0f - rho0,     om1  = 1.0f - rho1;

    size_t base = ((size_t)b * (size_t)S + (size_t)g * (size_t)L) * (size_t)F
                + (size_t)(f2 << 1);
    const float2* pr  = (const float2*)(fr + base);
    const float2* pim = (const float2*)(fi + base);
    size_t st = (size_t)F2;              // float2 stride per step

    float C0 = 0.0f, C1 = 0.0f;
    float2 lxr = make_float2(0.f, 0.f), lxi = make_float2(0.f, 0.f);

    int nch = L / UNR;
    float2 cr[UNR], ci[UNR];
#pragma unroll
    for (int k = 0; k < UNR; ++k) {
        cr[k] = __ldcs(pr  + (size_t)k * st);
        ci[k] = __ldcs(pim + (size_t)k * st);
    }
    pr  += (size_t)UNR * st;
    pim += (size_t)UNR * st;

#pragma unroll 1
    for (int j = 0; j < nch; ++j) {
        float2 nr[UNR], ni[UNR];
        if (j + 1 < nch) {
#pragma unroll
            for (int k = 0; k < UNR; ++k) {
                nr[k] = __ldcs(pr  + (size_t)k * st);
                ni[k] = __ldcs(pim + (size_t)k * st);
            }
            pr  += (size_t)UNR * st;
            pim += (size_t)UNR * st;
        }
#pragma unroll
        for (int k = 0; k < UNR; ++k) {
            float wa = mag_(cr[k].x, ci[k].x);
            float wb = mag_(cr[k].y, ci[k].y);
            C0 = fmaf(rho0, C0, om0 * wa);
            C1 = fmaf(rho1, C1, om1 * wb);
            lxr = cr[k]; lxi = ci[k];
        }
#pragma unroll
        for (int k = 0; k < UNR; ++k) { cr[k] = nr[k]; ci[k] = ni[k]; }
    }

    size_t bf0 = (size_t)b * (size_t)F + (size_t)(f2 << 1);
    *(float2*)(g_C + (size_t)g * MAX_BF + bf0) = make_float2(C0, C1);
    if (g == G - 1) {
        g_lx[bf0]     = make_float2(lxr.x, lxi.x);
        g_lx[bf0 + 1] = make_float2(lxr.y, lxi.y);
    }

    // ---- arrive: last block of this column does the combine ----
    __threadfence();          // publish g_C / g_lx (device scope)
    __syncthreads();
    __shared__ unsigned int s_last;
    int col = b * gridDim.x + blockIdx.x;
    if (threadIdx.x == 0) {
        unsigned int old = atomicAdd(&g_cnt[col], 1u);
        s_last = (old == (unsigned int)(G - 1)) ? 1u : 0u;
    }
    __syncthreads();
    if (!s_last) return;

    __threadfence();          // acquire other segments' g_C stores

    // ---- combine (rho0/rho1 already live in registers) ----
    float2 tw = __ldg((const float2*)theta_raw + f2);
    size_t bfh = (size_t)b * (size_t)F2 + (size_t)f2;   // float2 index into ir/ii
    float2 s0 = __ldg((const float2*)ir + bfh);
    float2 s1 = __ldg((const float2*)ii + bfh);
    float m0 = mag_(s0.x, s1.x);
    float m1 = mag_(s0.y, s1.y);

    if (tw.x == 0.0f && tw.y == 0.0f) {
        float D0 = __powf(rho0, (float)L);
        float D1 = __powf(rho1, (float)L);
#pragma unroll
        for (int q = 0; q < G; ++q) {
            float2 cv = *(const float2*)(g_C + (size_t)q * MAX_BF + bf0);
            m0 = fmaf(D0, m0, cv.x);
            m1 = fmaf(D1, m1, cv.y);
        }
        float2 lx0 = g_lx[bf0];
        float2 lx1 = g_lx[bf0 + 1];
        float w20 = fmaxf(fmaf(lx0.x, lx0.x, lx0.y * lx0.y), 1e-37f);
        float w21 = fmaxf(fmaf(lx1.x, lx1.x, lx1.y * lx1.y), 1e-37f);
        float sc0 = m0 * rsqrtf(w20);
        float sc1 = m1 * rsqrtf(w21);
        out[bf0]     = make_float2(lx0.x * sc0, lx0.y * sc0);
        out[bf0 + 1] = make_float2(lx1.x * sc1, lx1.y * sc1);
    } else {
        // general complex-a path (not taken for this dataset): full rescan
#pragma unroll 1
        for (int q = 0; q < 2; ++q) {
            int f = (f2 << 1) + q;
            float rho = (q == 0) ? rho0 : rho1;
            float th  = 3.14159265358979323846f * tanhf(q == 0 ? tw.x : tw.y);
            float ss, sc;
            sincosf(th, &ss, &sc);
            float ar = rho * sc, ai = rho * ss, omr = 1.0f - rho;
            float m  = (q == 0) ? m0 : m1;
            const float* p  = fr + (size_t)b * (size_t)S * (size_t)F + f;
            const float* pi = fi + (size_t)b * (size_t)S * (size_t)F + f;
            float zr = 0.f, zi = 0.f, rinv = 1.f, lr = 0.f, li = 0.f;
            for (int s = 0; s < S; ++s) {
                float xr = __ldg(p), xi = __ldg(pi);
                p += F; pi += F;
                float x2 = fmaxf(fmaf(xr, xr, xi * xi), 1e-37f);
                float rv = rsqrtf(x2);
                float w  = x2 * rv;
                zr = fmaf(ar, m, omr * w);
                zi = ai * m;
                m = mag_(zr, zi);
                rinv = rv; lr = xr; li = xi;
            }
            out[(size_t)b * F + f] =
                make_float2((zr * lr - zi * li) * rinv,
                            fmaf(zr, li, zi * lr) * rinv);
        }
    }

    // reset counter for the next graph replay (all arrivals already in)
    if (threadIdx.x == 0) g_cnt[col] = 0u;
}

// ---------------- Monolithic fallback (unexpected shapes) ----------------
__global__ __launch_bounds__(256)
void mono_kernel(const float* __restrict__ fr, const float* __restrict__ fi,
                 const float* __restrict__ ir, const float* __restrict__ ii,
                 const float* __restrict__ rho_logit,
                 const float* __restrict__ theta_raw,
                 float2* __restrict__ out, int S, int F)
{
    int f = blockIdx.x * blockDim.x + threadIdx.x;
    if (f >= F) return;
    int b = blockIdx.y;
    size_t bf = (size_t)b * (size_t)F + (size_t)f;

    float rho = sigmoidf_(rho_logit[f]);
    float th  = 3.14159265358979323846f * tanhf(theta_raw[f]);
    float ss, sc;
    sincosf(th, &ss, &sc);
    float ar = rho * sc, ai = rho * ss, omr = 1.0f - rho;

    float srv = ir[bf], siv = ii[bf];
    float m = mag_(srv, siv);

    const float* pr  = fr + (size_t)b * (size_t)S * (size_t)F + f;
    const float* pim = fi + (size_t)b * (size_t)S * (size_t)F + f;
    float zr = 0.f, zi = 0.f, rinv = 1.f, lxr = 0.f, lxi = 0.f;
    for (int s = 0; s < S; ++s) {
        float xr = __ldcs(pr), xi = __ldcs(pim);
        pr += F; pim += F;
        float x2 = fmaxf(fmaf(xr, xr, xi * xi), 1e-37f);
        float rv = rsqrtf(x2);
        float w  = x2 * rv;
        zr = fmaf(ar, m, omr * w);
        zi = ai * m;
        m = mag_(zr, zi);
        rinv = rv; lxr = xr; lxi = xi;
    }
    out[bf] = make_float2((zr * lxr - zi * lxi) * rinv,
                          fmaf(zr, lxi, zi * lxr) * rinv);
}

extern "C" void kernel_launch(void* const* d_in, const int* in_sizes, int n_in,
                              void* d_out, int out_size)
{
    const float* fr = (const float*)d_in[0];
    const float* fi = (const float*)d_in[1];
    const float* ir = (const float*)d_in[2];
    const float* ii = (const float*)d_in[3];
    const float* rl = (const float*)d_in[4];
    const float* tr = (const float*)d_in[5];

    int F  = in_sizes[4];
    int BF = in_sizes[2];
    int B  = BF / F;
    int S  = in_sizes[0] / BF;

    dim3 block(256);

    bool fast = (BF <= MAX_BF) && (F % 512 == 0) && (S % (G * UNR) == 0);
    if (fast) {
        int L  = S / G;
        int F2 = F / 2;
        dim3 grid(F2 / 256, B, G);
        fused_kernel<<<grid, block>>>(fr, fi, ir, ii, rl, tr,
                                      (float2*)d_out, S, F, L);
    } else {
        dim3 grid((F + 255) / 256, B);
        mono_kernel<<<grid, block>>>(fr, fi, ir, ii, rl, tr,
                                     (float2*)d_out, S, F);
    }
}